// round 5
// baseline (speedup 1.0000x reference)
#include <cuda_runtime.h>
#include <math.h>
#include <stdint.h>

#define BB   64
#define TT   128
#define DD   850
#define D2   1700
#define CIN  910
#define NCC  42
#define NNER 30
#define NPOS 30
#define SD   864          // padded state stride (27*32); cols >= 850 stay zero
#define NTILE 54          // ceil(850/16) column-pair tiles
#define NCHUNK 27         // SD/32 k-chunks

// Scratch (device globals zero-initialized; pad columns never written)
__device__ float g_combined[TT * BB * CIN];
__device__ float g_x[TT * BB * DD];
__device__ float g_xw0[TT * BB * D2];
__device__ float g_hiddens[TT * BB * DD];
__device__ float g_state[9][BB * SD];
__device__ float g_hprev[BB * SD];
__device__ float g_part[3][4][BB * D2];
__device__ int   g_cnt[3][NTILE];
__device__ unsigned g_bar_cnt;
__device__ unsigned g_bar_gen;

struct StepInfo { int wmat; int pred; int act; };
// act: 0 tanh, 1 relu, 2 sigmoid, 3 identity
__constant__ StepInfo c_steps[9] = {
    {0, -1, 0},  // s0 cell (tanh)
    {1,  0, 2},  // s1 sigmoid
    {2,  1, 1},  // s2 relu
    {3,  1, 1},  // s3 relu
    {4,  1, 3},  // s4 identity
    {5,  2, 0},  // s5 tanh
    {6,  5, 2},  // s6 sigmoid
    {7,  3, 0},  // s7 tanh
    {8,  5, 1},  // s8 relu
};
__constant__ int c_nm[5]    = {1, 1, 3, 2, 2};
__constant__ int c_sk[5]    = {4, 4, 1, 2, 2};
__constant__ int c_sid[5][3] = {{0,0,0},{1,1,1},{2,3,4},{5,7,7},{6,8,8}};

__device__ __forceinline__ void cp_async16(uint32_t dst, const void* src) {
    asm volatile("cp.async.ca.shared.global [%0], [%1], 16;\n" :: "r"(dst), "l"(src));
}

// Sense-reversing grid barrier (all gridDim.x CTAs must be co-resident).
__device__ __forceinline__ void grid_sync() {
    __syncthreads();
    if (threadIdx.x == 0) {
        __threadfence();
        volatile unsigned* vg = &g_bar_gen;
        unsigned gen = *vg;
        if (atomicAdd(&g_bar_cnt, 1u) == gridDim.x - 1) {
            g_bar_cnt = 0;
            __threadfence();
            atomicExch(&g_bar_gen, gen + 1u);
        } else {
            while (*vg == gen) { __nanosleep(64); }
        }
        __threadfence();
    }
    __syncthreads();
}

// ---------------------------------------------------------------------------
// K1: gather embeddings into g_combined rows (r = t*BB + b)
// ---------------------------------------------------------------------------
__global__ void gather_kernel(const int* __restrict__ tokens,
                              const int* __restrict__ ner,
                              const int* __restrict__ pos,
                              const float* __restrict__ encW,
                              const float* __restrict__ nerW,
                              const float* __restrict__ posW) {
    int r = blockIdx.x;
    int b = r & (BB - 1);
    int t = r >> 6;
    int tok = tokens[b * TT + t];
    int nid = ner[b * TT + t];
    int pid = pos[b * TT + t];
    float* dst = g_combined + (size_t)r * CIN;
    for (int c = threadIdx.x; c < CIN; c += blockDim.x) {
        float v;
        if (c < DD)             v = encW[(size_t)tok * DD + c];
        else if (c < DD + NNER) v = nerW[nid * NNER + (c - DD)];
        else                    v = posW[pid * NPOS + (c - DD - NNER)];
        dst[c] = v;
    }
}

// ---------------------------------------------------------------------------
// K2: generic tiled fp32 GEMM, C = A * op(B) (+ bias). BM=BN=64, BK=16.
// ---------------------------------------------------------------------------
template <bool TRANSB, bool ADDBIAS>
__global__ void gemm_tile(const float* __restrict__ A, const float* __restrict__ Bm,
                          const float* __restrict__ bias, float* __restrict__ C,
                          int M, int N, int K, int lda, int ldb, int ldc) {
    __shared__ __align__(16) float As[16 * 64];
    __shared__ __align__(16) float Bs[16 * 64];
    int tid = threadIdx.x;
    int m0 = blockIdx.y * 64;
    int n0 = blockIdx.x * 64;
    int mi = tid & 15;
    int ni = tid >> 4;
    float acc[4][4] = {};

    for (int k0 = 0; k0 < K; k0 += 16) {
        __syncthreads();
        #pragma unroll
        for (int i = 0; i < 4; i++) {
            int e = tid + 256 * i;
            int m = e >> 4, k = e & 15;
            int kk = k0 + k;
            float v = 0.f;
            if (kk < K) v = A[(size_t)(m0 + m) * lda + kk];
            As[k * 64 + m] = v;
        }
        #pragma unroll
        for (int i = 0; i < 4; i++) {
            int e = tid + 256 * i;
            float v = 0.f;
            if (TRANSB) {
                int n = e >> 4, k = e & 15;
                int kk = k0 + k, nn = n0 + n;
                if (kk < K && nn < N) v = Bm[(size_t)nn * ldb + kk];
                Bs[k * 64 + n] = v;
            } else {
                int k = e >> 6, n = e & 63;
                int kk = k0 + k, nn = n0 + n;
                if (kk < K && nn < N) v = Bm[(size_t)kk * ldb + nn];
                Bs[k * 64 + n] = v;
            }
        }
        __syncthreads();
        #pragma unroll
        for (int k = 0; k < 16; k++) {
            float4 a4 = *(const float4*)(As + k * 64 + mi * 4);
            float4 b4 = *(const float4*)(Bs + k * 64 + ni * 4);
            acc[0][0] = fmaf(a4.x, b4.x, acc[0][0]);
            acc[0][1] = fmaf(a4.x, b4.y, acc[0][1]);
            acc[0][2] = fmaf(a4.x, b4.z, acc[0][2]);
            acc[0][3] = fmaf(a4.x, b4.w, acc[0][3]);
            acc[1][0] = fmaf(a4.y, b4.x, acc[1][0]);
            acc[1][1] = fmaf(a4.y, b4.y, acc[1][1]);
            acc[1][2] = fmaf(a4.y, b4.z, acc[1][2]);
            acc[1][3] = fmaf(a4.y, b4.w, acc[1][3]);
            acc[2][0] = fmaf(a4.z, b4.x, acc[2][0]);
            acc[2][1] = fmaf(a4.z, b4.y, acc[2][1]);
            acc[2][2] = fmaf(a4.z, b4.z, acc[2][2]);
            acc[2][3] = fmaf(a4.z, b4.w, acc[2][3]);
            acc[3][0] = fmaf(a4.w, b4.x, acc[3][0]);
            acc[3][1] = fmaf(a4.w, b4.y, acc[3][1]);
            acc[3][2] = fmaf(a4.w, b4.z, acc[3][2]);
            acc[3][3] = fmaf(a4.w, b4.w, acc[3][3]);
        }
    }
    #pragma unroll
    for (int r = 0; r < 4; r++) {
        int mm = m0 + mi * 4 + r;
        #pragma unroll
        for (int c = 0; c < 4; c++) {
            int nn = n0 + ni * 4 + c;
            if (nn < N) {
                float v = acc[r][c];
                if (ADDBIAS) v += bias[nn];
                C[(size_t)mm * ldc + nn] = v;
            }
        }
    }
}

// ---------------------------------------------------------------------------
// Persistent recurrence: one tile-job = [64 rows x 16 col-pairs] x k-range.
// ---------------------------------------------------------------------------
struct SmemBuf {
    float As[2][64][32];
    int   s_old;
};

__device__ __forceinline__ void do_tile(
    int t, int sid, int mat, int tile, int kh, int sk,
    const float* __restrict__ W0, const float* __restrict__ Ws, SmemBuf* sm)
{
    const StepInfo si = c_steps[sid];
    const float* __restrict__ W = (si.wmat == 0)
        ? (W0 + (size_t)DD * D2)
        : (Ws + (size_t)(si.wmat - 1) * DD * D2);
    const float* __restrict__ A = (si.pred < 0) ? g_hprev : g_state[si.pred];

    const int p0 = tile * 16;
    const int tid = threadIdx.x;
    const int cp = tid & 15;
    const int mb = tid >> 4;
    const int p = p0 + cp;
    const bool pv = (p < DD);
    const int pc = pv ? p : 0;
    const int ph = pc + DD;

    const int cbeg = (NCHUNK * kh) / sk;
    const int cend = (NCHUNK * (kh + 1)) / sk;
    const int nch = cend - cbeg;

    const int srow = tid >> 2;
    const int sseg = (tid & 3) * 8;
    const float* gsrc = A + (size_t)srow * SD + sseg;

    float accC[4] = {0.f, 0.f, 0.f, 0.f};
    float accH[4] = {0.f, 0.f, 0.f, 0.f};

    {
        uint32_t dst = (uint32_t)__cvta_generic_to_shared(&sm->As[0][srow][sseg]);
        const float* src = gsrc + cbeg * 32;
        cp_async16(dst, src);
        cp_async16(dst + 16, src + 4);
        asm volatile("cp.async.commit_group;\n");
    }

    for (int c = 0; c < nch; ++c) {
        const int cb = c & 1;
        if (c + 1 < nch) {
            uint32_t dst = (uint32_t)__cvta_generic_to_shared(&sm->As[cb ^ 1][srow][sseg]);
            const float* src = gsrc + (cbeg + c + 1) * 32;
            cp_async16(dst, src);
            cp_async16(dst + 16, src + 4);
            asm volatile("cp.async.commit_group;\n");
            asm volatile("cp.async.wait_group 1;\n");
        } else {
            asm volatile("cp.async.wait_group 0;\n");
        }
        __syncthreads();

        const int kg = (cbeg + c) * 32;
        if (kg + 32 <= DD) {
            const float* wrow = W + (size_t)kg * D2;
            #pragma unroll
            for (int q = 0; q < 8; ++q) {
                float4 a0 = *(const float4*)&sm->As[cb][mb * 4 + 0][q * 4];
                float4 a1 = *(const float4*)&sm->As[cb][mb * 4 + 1][q * 4];
                float4 a2 = *(const float4*)&sm->As[cb][mb * 4 + 2][q * 4];
                float4 a3 = *(const float4*)&sm->As[cb][mb * 4 + 3][q * 4];
                float wc0 = wrow[pc], wh0 = wrow[ph];
                const float* w1 = wrow + D2;
                float wc1 = w1[pc], wh1 = w1[ph];
                const float* w2 = w1 + D2;
                float wc2 = w2[pc], wh2 = w2[ph];
                const float* w3 = w2 + D2;
                float wc3 = w3[pc], wh3 = w3[ph];
                wrow = w3 + D2;
                accC[0] = fmaf(a0.x, wc0, fmaf(a0.y, wc1, fmaf(a0.z, wc2, fmaf(a0.w, wc3, accC[0]))));
                accC[1] = fmaf(a1.x, wc0, fmaf(a1.y, wc1, fmaf(a1.z, wc2, fmaf(a1.w, wc3, accC[1]))));
                accC[2] = fmaf(a2.x, wc0, fmaf(a2.y, wc1, fmaf(a2.z, wc2, fmaf(a2.w, wc3, accC[2]))));
                accC[3] = fmaf(a3.x, wc0, fmaf(a3.y, wc1, fmaf(a3.z, wc2, fmaf(a3.w, wc3, accC[3]))));
                accH[0] = fmaf(a0.x, wh0, fmaf(a0.y, wh1, fmaf(a0.z, wh2, fmaf(a0.w, wh3, accH[0]))));
                accH[1] = fmaf(a1.x, wh0, fmaf(a1.y, wh1, fmaf(a1.z, wh2, fmaf(a1.w, wh3, accH[1]))));
                accH[2] = fmaf(a2.x, wh0, fmaf(a2.y, wh1, fmaf(a2.z, wh2, fmaf(a2.w, wh3, accH[2]))));
                accH[3] = fmaf(a3.x, wh0, fmaf(a3.y, wh1, fmaf(a3.z, wh2, fmaf(a3.w, wh3, accH[3]))));
            }
        } else {
            #pragma unroll 4
            for (int kk = 0; kk < 32; ++kk) {
                int k = kg + kk;
                int wk = (k < DD) ? k : (DD - 1);
                float wc = W[(size_t)wk * D2 + pc];
                float wh = W[(size_t)wk * D2 + ph];
                #pragma unroll
                for (int r = 0; r < 4; ++r) {
                    float a = sm->As[cb][mb * 4 + r][kk];
                    accC[r] = fmaf(a, wc, accC[r]);
                    accH[r] = fmaf(a, wh, accH[r]);
                }
            }
        }
        __syncthreads();
    }

    // split-K: write own partial, last arriver combines all in fixed order.
    float* pt = g_part[mat][kh];
    if (pv) {
        #pragma unroll
        for (int r = 0; r < 4; ++r) {
            int m = mb * 4 + r;
            pt[(size_t)m * D2 + p]      = accC[r];
            pt[(size_t)m * D2 + DD + p] = accH[r];
        }
    }
    __threadfence();
    __syncthreads();
    if (tid == 0) sm->s_old = atomicAdd(&g_cnt[mat][tile], 1);
    __syncthreads();
    if (sm->s_old == sk - 1) {
        __threadfence();
        if (pv) {
            #pragma unroll
            for (int r = 0; r < 4; ++r) {
                int m = mb * 4 + r;
                float cc = 0.f, hh = 0.f;
                for (int q = 0; q < sk; ++q) {
                    cc += g_part[mat][q][(size_t)m * D2 + p];
                    hh += g_part[mat][q][(size_t)m * D2 + DD + p];
                }
                if (si.pred < 0) {
                    const float* xw = g_xw0 + ((size_t)t * BB + m) * D2;
                    cc += __ldcs(xw + p);
                    hh += __ldcs(xw + DD + p);
                }
                float sp = A[(size_t)m * SD + p];
                float g = 1.f / (1.f + expf(-cc));
                float av = (si.act == 0) ? tanhf(hh)
                         : (si.act == 1) ? fmaxf(hh, 0.f)
                         : (si.act == 2) ? 1.f / (1.f + expf(-hh)) : hh;
                g_state[sid][(size_t)m * SD + p] = sp + g * (av - sp);
            }
        }
        __syncthreads();
        if (tid == 0) g_cnt[mat][tile] = 0;
    }
    __syncthreads();
}

__global__ __launch_bounds__(256, 2)
void recur_persist(const float* __restrict__ W0, const float* __restrict__ Ws,
                   const float* __restrict__ hidden) {
    __shared__ SmemBuf sm;
    const int bid = blockIdx.x;
    const int G = gridDim.x;
    const int tid = threadIdx.x;

    for (int t = 0; t < TT; ++t) {
        // prep phase: hprev = (t==0) ? hidden : mean(s1..s8); emit hiddens[t-1]
        for (int i = bid * 256 + tid; i < BB * DD; i += G * 256) {
            int m = i / DD;
            int d = i - m * DD;
            float v;
            if (t == 0) {
                v = hidden[i];
            } else {
                float s = 0.f;
                #pragma unroll
                for (int j = 1; j <= 8; j++) s += g_state[j][m * SD + d];
                v = s * 0.125f;
                __stcs(&g_hiddens[(size_t)(t - 1) * BB * DD + i], v);
            }
            g_hprev[m * SD + d] = v;
        }
        grid_sync();

        #pragma unroll
        for (int lvl = 0; lvl < 5; ++lvl) {
            const int nm = c_nm[lvl];
            const int sk = c_sk[lvl];
            const int jobs = nm * sk * NTILE;
            for (int j = bid; j < jobs; j += G) {
                int tile = j % NTILE;
                int r = j / NTILE;
                int kh = r % sk;
                int mat = r / sk;
                do_tile(t, c_sid[lvl][mat], mat, tile, kh, sk, W0, Ws, &sm);
            }
            grid_sync();
        }
    }
}

// ---------------------------------------------------------------------------
// K5: mean over T, decoder, log_softmax, new_hidden. One block per batch elem.
// out[0 : 64*42) = log_prob ; out[64*42 : ) = new_hidden [64*850]
// ---------------------------------------------------------------------------
__global__ void final_kernel(const float* __restrict__ masks,
                             const float* __restrict__ decW,
                             const float* __restrict__ decb,
                             float* __restrict__ out) {
    int b = blockIdx.x;
    int tid = threadIdx.x;
    __shared__ float sout[DD];
    __shared__ float lg[NCC];
    __shared__ float lse;

    float mask_last = masks[b * TT + TT - 1];
    for (int d = tid; d < DD; d += blockDim.x) {
        float ms = 0.f;
        #pragma unroll
        for (int j = 1; j <= 8; j++) ms += g_state[j][b * SD + d];
        ms *= 0.125f;
        float last_raw = ms * mask_last;
        float acc = last_raw;
        for (int t = 0; t < TT - 1; t++)
            acc += g_hiddens[(size_t)t * BB * DD + b * DD + d] * masks[b * TT + t];
        sout[d] = acc * (1.f / TT);
        out[NCC * BB + b * DD + d] = last_raw;
    }
    __syncthreads();

    for (int c = tid; c < NCC; c += blockDim.x) {
        float acc = decb[c];
        const float* w = decW + (size_t)c * DD;
        for (int d = 0; d < DD; d++) acc = fmaf(sout[d], w[d], acc);
        lg[c] = acc;
    }
    __syncthreads();

    if (tid == 0) {
        float mx = lg[0];
        for (int c = 1; c < NCC; c++) mx = fmaxf(mx, lg[c]);
        float s = 0.f;
        for (int c = 0; c < NCC; c++) s += expf(lg[c] - mx);
        lse = mx + logf(s);
    }
    __syncthreads();

    for (int c = tid; c < NCC; c += blockDim.x)
        out[b * NCC + c] = lg[c] - lse;
}

// ---------------------------------------------------------------------------
// Host launcher
// ---------------------------------------------------------------------------
extern "C" void kernel_launch(void* const* d_in, const int* in_sizes, int n_in,
                              void* d_out, int out_size) {
    const int*   tokens = (const int*)  d_in[0];
    const float* masks  = (const float*)d_in[1];
    const int*   pos    = (const int*)  d_in[2];
    const int*   ner    = (const int*)  d_in[3];
    const float* hidden = (const float*)d_in[4];
    const float* encW   = (const float*)d_in[5];
    const float* nerW   = (const float*)d_in[6];
    const float* posW   = (const float*)d_in[7];
    const float* aggW   = (const float*)d_in[8];
    const float* aggb   = (const float*)d_in[9];
    const float* W0     = (const float*)d_in[10];
    const float* Ws     = (const float*)d_in[11];
    const float* decW   = (const float*)d_in[12];
    const float* decb   = (const float*)d_in[13];
    float* out = (float*)d_out;

    static int s_grid = 0;
    if (s_grid == 0) {
        int dev = 0;
        cudaGetDevice(&dev);
        cudaDeviceProp prop;
        cudaGetDeviceProperties(&prop, dev);
        s_grid = 2 * prop.multiProcessorCount;   // co-resident by __launch_bounds__(256,2)
    }

    float *p_combined, *p_x, *p_xw0;
    cudaGetSymbolAddress((void**)&p_combined, g_combined);
    cudaGetSymbolAddress((void**)&p_x,        g_x);
    cudaGetSymbolAddress((void**)&p_xw0,      g_xw0);

    // 1) gather embeddings
    gather_kernel<<<TT * BB, 128>>>(tokens, ner, pos, encW, nerW, posW);

    // 2) agg linear: x = combined @ aggW^T + aggb   [8192, 850]
    {
        dim3 g((DD + 63) / 64, (TT * BB) / 64);
        gemm_tile<true, true><<<g, 256>>>(p_combined, aggW, aggb, p_x,
                                          TT * BB, DD, CIN, CIN, CIN, DD);
    }
    // 3) xw0 = x @ W0[0:DD, :]   [8192, 1700]
    {
        dim3 g((D2 + 63) / 64, (TT * BB) / 64);
        gemm_tile<false, false><<<g, 256>>>(p_x, W0, nullptr, p_xw0,
                                            TT * BB, D2, DD, DD, D2, D2);
    }

    // 4) whole recurrence in ONE persistent kernel (barriers between phases)
    recur_persist<<<s_grid, 256>>>(W0, Ws, hidden);

    // 5) mean over T, decoder, log_softmax, new_hidden
    final_kernel<<<BB, 256>>>(masks, decW, decb, out);
}

// round 9
// speedup vs baseline: 1.0816x; 1.0816x over previous
#include <cuda_runtime.h>
#include <cuda_bf16.h>
#include <math.h>
#include <stdint.h>

#define BB   64
#define TT   128
#define DD   850
#define D2   1700
#define CIN  910
#define NCC  42
#define NNER 30
#define NPOS 30
#define SD   864          // padded k stride; pads stay zero
#define NTILE 54          // 16-col tiles
#define NCHUNK 27         // 32-wide k chunks (27*32 = 864)
#define PD2  1728         // padded partial width: c half at 0, h half at 864

// Scratch (device globals zero-initialized; pad regions never written)
__device__ float g_combined[TT * BB * CIN];
__device__ float g_x[TT * BB * DD];
__device__ float g_xw0[TT * BB * D2];
__device__ float g_hiddens[TT * BB * DD];
__device__ float g_state[9][BB * SD];
__device__ float g_hprev[BB * SD];
__device__ __align__(256) float g_part[3][5][BB * PD2];
__device__ int   g_cnt[3][NTILE];
__device__ unsigned g_bar_cnt;
__device__ unsigned g_bar_gen;
// A splits kept for skeleton fidelity (written, unread by fp32 engine)
__device__ __align__(256) __nv_bfloat16 g_as[10][3][BB * SD];

struct StepInfo { int wmat; int pred; int act; };
// act: 0 tanh, 1 relu, 2 sigmoid, 3 identity
__constant__ StepInfo c_steps[9] = {
    {0, -1, 0}, {1, 0, 2}, {2, 1, 1}, {3, 1, 1}, {4, 1, 3},
    {5, 2, 0}, {6, 5, 2}, {7, 3, 0}, {8, 5, 1},
};
// Levels: {s0},{s1},{s2,s3,s4},{s5},{s6,s7,s8}
__constant__ int c_nm[5]     = {1, 1, 3, 1, 3};
__constant__ int c_sk[5]     = {5, 5, 3, 5, 3};
__constant__ int c_sid[5][3] = {{0,0,0},{1,1,1},{2,3,4},{5,5,5},{6,7,8}};

__device__ __forceinline__ void cp_async16(uint32_t dst, const void* src) {
    asm volatile("cp.async.ca.shared.global [%0], [%1], 16;\n" :: "r"(dst), "l"(src));
}

// Sense-reversing grid barrier (all CTAs co-resident).
__device__ __forceinline__ void grid_sync() {
    __syncthreads();
    if (threadIdx.x == 0) {
        __threadfence();
        volatile unsigned* vg = &g_bar_gen;
        unsigned gen = *vg;
        if (atomicAdd(&g_bar_cnt, 1u) == gridDim.x - 1) {
            g_bar_cnt = 0;
            __threadfence();
            atomicExch(&g_bar_gen, gen + 1u);
        } else {
            while (*vg == gen) { __nanosleep(64); }
        }
        __threadfence();
    }
    __syncthreads();
}

__device__ __forceinline__ void split3(float x, __nv_bfloat16& b1,
                                       __nv_bfloat16& b2, __nv_bfloat16& b3) {
    b1 = __float2bfloat16_rn(x);
    float r = x - __bfloat162float(b1);
    b2 = __float2bfloat16_rn(r);
    r -= __bfloat162float(b2);
    b3 = __float2bfloat16_rn(r);
}

// ---------------------------------------------------------------------------
// K1: gather embeddings
// ---------------------------------------------------------------------------
__global__ void gather_kernel(const int* __restrict__ tokens,
                              const int* __restrict__ ner,
                              const int* __restrict__ pos,
                              const float* __restrict__ encW,
                              const float* __restrict__ nerW,
                              const float* __restrict__ posW) {
    int r = blockIdx.x;
    int b = r & (BB - 1);
    int t = r >> 6;
    int tok = tokens[b * TT + t];
    int nid = ner[b * TT + t];
    int pid = pos[b * TT + t];
    float* dst = g_combined + (size_t)r * CIN;
    for (int c = threadIdx.x; c < CIN; c += blockDim.x) {
        float v;
        if (c < DD)             v = encW[(size_t)tok * DD + c];
        else if (c < DD + NNER) v = nerW[nid * NNER + (c - DD)];
        else                    v = posW[pid * NPOS + (c - DD - NNER)];
        dst[c] = v;
    }
}

// ---------------------------------------------------------------------------
// K2: generic tiled fp32 GEMM (pre-GEMMs)
// ---------------------------------------------------------------------------
template <bool TRANSB, bool ADDBIAS>
__global__ void gemm_tile(const float* __restrict__ A, const float* __restrict__ Bm,
                          const float* __restrict__ bias, float* __restrict__ C,
                          int M, int N, int K, int lda, int ldb, int ldc) {
    __shared__ __align__(16) float As[16 * 64];
    __shared__ __align__(16) float Bs[16 * 64];
    int tid = threadIdx.x;
    int m0 = blockIdx.y * 64;
    int n0 = blockIdx.x * 64;
    int mi = tid & 15;
    int ni = tid >> 4;
    float acc[4][4] = {};

    for (int k0 = 0; k0 < K; k0 += 16) {
        __syncthreads();
        #pragma unroll
        for (int i = 0; i < 4; i++) {
            int e = tid + 256 * i;
            int m = e >> 4, k = e & 15;
            int kk = k0 + k;
            float v = 0.f;
            if (kk < K) v = A[(size_t)(m0 + m) * lda + kk];
            As[k * 64 + m] = v;
        }
        #pragma unroll
        for (int i = 0; i < 4; i++) {
            int e = tid + 256 * i;
            float v = 0.f;
            if (TRANSB) {
                int n = e >> 4, k = e & 15;
                int kk = k0 + k, nn = n0 + n;
                if (kk < K && nn < N) v = Bm[(size_t)nn * ldb + kk];
                Bs[k * 64 + n] = v;
            } else {
                int k = e >> 6, n = e & 63;
                int kk = k0 + k, nn = n0 + n;
                if (kk < K && nn < N) v = Bm[(size_t)kk * ldb + nn];
                Bs[k * 64 + n] = v;
            }
        }
        __syncthreads();
        #pragma unroll
        for (int k = 0; k < 16; k++) {
            float4 a4 = *(const float4*)(As + k * 64 + mi * 4);
            float4 b4 = *(const float4*)(Bs + k * 64 + ni * 4);
            acc[0][0] = fmaf(a4.x, b4.x, acc[0][0]);
            acc[0][1] = fmaf(a4.x, b4.y, acc[0][1]);
            acc[0][2] = fmaf(a4.x, b4.z, acc[0][2]);
            acc[0][3] = fmaf(a4.x, b4.w, acc[0][3]);
            acc[1][0] = fmaf(a4.y, b4.x, acc[1][0]);
            acc[1][1] = fmaf(a4.y, b4.y, acc[1][1]);
            acc[1][2] = fmaf(a4.y, b4.z, acc[1][2]);
            acc[1][3] = fmaf(a4.y, b4.w, acc[1][3]);
            acc[2][0] = fmaf(a4.z, b4.x, acc[2][0]);
            acc[2][1] = fmaf(a4.z, b4.y, acc[2][1]);
            acc[2][2] = fmaf(a4.z, b4.z, acc[2][2]);
            acc[2][3] = fmaf(a4.z, b4.w, acc[2][3]);
            acc[3][0] = fmaf(a4.w, b4.x, acc[3][0]);
            acc[3][1] = fmaf(a4.w, b4.y, acc[3][1]);
            acc[3][2] = fmaf(a4.w, b4.z, acc[3][2]);
            acc[3][3] = fmaf(a4.w, b4.w, acc[3][3]);
        }
    }
    #pragma unroll
    for (int r = 0; r < 4; r++) {
        int mm = m0 + mi * 4 + r;
        #pragma unroll
        for (int c = 0; c < 4; c++) {
            int nn = n0 + ni * 4 + c;
            if (nn < N) {
                float v = acc[r][c];
                if (ADDBIAS) v += bias[nn];
                C[(size_t)mm * ldc + nn] = v;
            }
        }
    }
}

// ---------------------------------------------------------------------------
// fp32 tile-job (R4 engine) inside the R7 skeleton; partials in PD2 layout.
// ---------------------------------------------------------------------------
struct SmemBuf {
    float As[2][64][32];
    int   s_old;
};

__device__ __forceinline__ void do_tile(
    int t, int sid, int mat, int tile, int kh, int sk,
    const float* __restrict__ W0, const float* __restrict__ Ws, SmemBuf* sm)
{
    const StepInfo si = c_steps[sid];
    const float* __restrict__ W = (si.wmat == 0)
        ? (W0 + (size_t)DD * D2)
        : (Ws + (size_t)(si.wmat - 1) * DD * D2);
    const float* __restrict__ Afp = (si.pred < 0) ? g_hprev : g_state[si.pred];

    const int p0 = tile * 16;
    const int tid = threadIdx.x;
    const int cp = tid & 15;
    const int mb = tid >> 4;
    const int p = p0 + cp;
    const bool pv = (p < DD);
    const int pc = pv ? p : 0;
    const int ph = pc + DD;

    const int cbeg = (NCHUNK * kh) / sk;
    const int cend = (NCHUNK * (kh + 1)) / sk;
    const int nch = cend - cbeg;

    const int srow = tid >> 2;
    const int sseg = (tid & 3) * 8;
    const float* gsrc = Afp + (size_t)srow * SD + sseg;

    float accC[4] = {0.f, 0.f, 0.f, 0.f};
    float accH[4] = {0.f, 0.f, 0.f, 0.f};

    {
        uint32_t dst = (uint32_t)__cvta_generic_to_shared(&sm->As[0][srow][sseg]);
        const float* src = gsrc + cbeg * 32;
        cp_async16(dst, src);
        cp_async16(dst + 16, src + 4);
        asm volatile("cp.async.commit_group;\n");
    }

    for (int c = 0; c < nch; ++c) {
        const int cb = c & 1;
        if (c + 1 < nch) {
            uint32_t dst = (uint32_t)__cvta_generic_to_shared(&sm->As[cb ^ 1][srow][sseg]);
            const float* src = gsrc + (cbeg + c + 1) * 32;
            cp_async16(dst, src);
            cp_async16(dst + 16, src + 4);
            asm volatile("cp.async.commit_group;\n");
            asm volatile("cp.async.wait_group 1;\n");
        } else {
            asm volatile("cp.async.wait_group 0;\n");
        }
        __syncthreads();

        const int kg = (cbeg + c) * 32;
        if (kg + 32 <= DD) {
            const float* wrow = W + (size_t)kg * D2;
            #pragma unroll
            for (int q = 0; q < 8; ++q) {
                float4 a0 = *(const float4*)&sm->As[cb][mb * 4 + 0][q * 4];
                float4 a1 = *(const float4*)&sm->As[cb][mb * 4 + 1][q * 4];
                float4 a2 = *(const float4*)&sm->As[cb][mb * 4 + 2][q * 4];
                float4 a3 = *(const float4*)&sm->As[cb][mb * 4 + 3][q * 4];
                float wc0 = wrow[pc], wh0 = wrow[ph];
                const float* w1 = wrow + D2;
                float wc1 = w1[pc], wh1 = w1[ph];
                const float* w2 = w1 + D2;
                float wc2 = w2[pc], wh2 = w2[ph];
                const float* w3 = w2 + D2;
                float wc3 = w3[pc], wh3 = w3[ph];
                wrow = w3 + D2;
                accC[0] = fmaf(a0.x, wc0, fmaf(a0.y, wc1, fmaf(a0.z, wc2, fmaf(a0.w, wc3, accC[0]))));
                accC[1] = fmaf(a1.x, wc0, fmaf(a1.y, wc1, fmaf(a1.z, wc2, fmaf(a1.w, wc3, accC[1]))));
                accC[2] = fmaf(a2.x, wc0, fmaf(a2.y, wc1, fmaf(a2.z, wc2, fmaf(a2.w, wc3, accC[2]))));
                accC[3] = fmaf(a3.x, wc0, fmaf(a3.y, wc1, fmaf(a3.z, wc2, fmaf(a3.w, wc3, accC[3]))));
                accH[0] = fmaf(a0.x, wh0, fmaf(a0.y, wh1, fmaf(a0.z, wh2, fmaf(a0.w, wh3, accH[0]))));
                accH[1] = fmaf(a1.x, wh0, fmaf(a1.y, wh1, fmaf(a1.z, wh2, fmaf(a1.w, wh3, accH[1]))));
                accH[2] = fmaf(a2.x, wh0, fmaf(a2.y, wh1, fmaf(a2.z, wh2, fmaf(a2.w, wh3, accH[2]))));
                accH[3] = fmaf(a3.x, wh0, fmaf(a3.y, wh1, fmaf(a3.z, wh2, fmaf(a3.w, wh3, accH[3]))));
            }
        } else {
            #pragma unroll 4
            for (int kk = 0; kk < 32; ++kk) {
                int k = kg + kk;
                int wk = (k < DD) ? k : (DD - 1);
                float wc = W[(size_t)wk * D2 + pc];
                float wh = W[(size_t)wk * D2 + ph];
                #pragma unroll
                for (int r = 0; r < 4; ++r) {
                    float a = sm->As[cb][mb * 4 + r][kk];
                    accC[r] = fmaf(a, wc, accC[r]);
                    accH[r] = fmaf(a, wh, accH[r]);
                }
            }
        }
        __syncthreads();
    }

    // partials in PD2 layout (c at p, h at 864+p)
    if (pv) {
        float* pt = g_part[mat][kh];
        #pragma unroll
        for (int r = 0; r < 4; ++r) {
            int m = mb * 4 + r;
            pt[(size_t)m * PD2 + p]       = accC[r];
            pt[(size_t)m * PD2 + 864 + p] = accH[r];
        }
    }

    __threadfence();
    __syncthreads();
    if (tid == 0) sm->s_old = atomicAdd(&g_cnt[mat][tile], 1);
    __syncthreads();
    if (sm->s_old == sk - 1) {
        __threadfence();
        // R7 epilogue, verbatim
        const int q = tid & 7;
        const int mq = tid >> 3;
        const int q0 = tile * 16 + 2 * q;
        if (q0 < DD) {
            #pragma unroll
            for (int h2 = 0; h2 < 2; ++h2) {
                int m = mq + h2 * 32;
                float vv[2];
                #pragma unroll
                for (int e = 0; e < 2; ++e) {
                    int pp = q0 + e;
                    float cc = 0.f, hh = 0.f;
                    for (int q2 = 0; q2 < sk; ++q2) {
                        cc += g_part[mat][q2][(size_t)m * PD2 + pp];
                        hh += g_part[mat][q2][(size_t)m * PD2 + 864 + pp];
                    }
                    if (si.pred < 0) {
                        const float* xw = g_xw0 + ((size_t)t * BB + m) * D2;
                        cc += __ldcs(xw + pp);
                        hh += __ldcs(xw + DD + pp);
                    }
                    float sp = Afp[(size_t)m * SD + pp];
                    float g = 1.f / (1.f + expf(-cc));
                    float av = (si.act == 0) ? tanhf(hh)
                             : (si.act == 1) ? fmaxf(hh, 0.f)
                             : (si.act == 2) ? 1.f / (1.f + expf(-hh)) : hh;
                    vv[e] = sp + g * (av - sp);
                }
                *(float2*)&g_state[sid][(size_t)m * SD + q0] = make_float2(vv[0], vv[1]);
                __nv_bfloat16 a1, a2, a3, b1, b2, b3;
                split3(vv[0], a1, a2, a3);
                split3(vv[1], b1, b2, b3);
                __nv_bfloat162 t1, t2, t3;
                t1.x = a1; t1.y = b1;
                t2.x = a2; t2.y = b2;
                t3.x = a3; t3.y = b3;
                *(__nv_bfloat162*)&g_as[sid][0][(size_t)m * SD + q0] = t1;
                *(__nv_bfloat162*)&g_as[sid][1][(size_t)m * SD + q0] = t2;
                *(__nv_bfloat162*)&g_as[sid][2][(size_t)m * SD + q0] = t3;
            }
        }
        __syncthreads();
        if (tid == 0) g_cnt[mat][tile] = 0;
    }
    __syncthreads();
}

__global__ __launch_bounds__(256, 2)
void recur_persist(const float* __restrict__ W0, const float* __restrict__ Ws,
                   const float* __restrict__ hidden) {
    __shared__ SmemBuf sm;
    const int bid = blockIdx.x;
    const int G = gridDim.x;
    const int tid = threadIdx.x;

    for (int t = 0; t < TT; ++t) {
        // R7 prep, verbatim
        for (int i = bid * 256 + tid; i < BB * 425; i += G * 256) {
            int m = i / 425;
            int qd = i - m * 425;
            int d0 = 2 * qd;
            float v0, v1;
            if (t == 0) {
                v0 = hidden[m * DD + d0];
                v1 = hidden[m * DD + d0 + 1];
            } else {
                float s0 = 0.f, s1 = 0.f;
                #pragma unroll
                for (int j = 1; j <= 8; j++) {
                    s0 += g_state[j][m * SD + d0];
                    s1 += g_state[j][m * SD + d0 + 1];
                }
                v0 = s0 * 0.125f;
                v1 = s1 * 0.125f;
                __stcs(&g_hiddens[(size_t)(t - 1) * BB * DD + m * DD + d0], v0);
                __stcs(&g_hiddens[(size_t)(t - 1) * BB * DD + m * DD + d0 + 1], v1);
            }
            *(float2*)&g_hprev[m * SD + d0] = make_float2(v0, v1);
            __nv_bfloat16 a1, a2, a3, b1, b2, b3;
            split3(v0, a1, a2, a3);
            split3(v1, b1, b2, b3);
            __nv_bfloat162 t1, t2, t3;
            t1.x = a1; t1.y = b1;
            t2.x = a2; t2.y = b2;
            t3.x = a3; t3.y = b3;
            *(__nv_bfloat162*)&g_as[9][0][(size_t)m * SD + d0] = t1;
            *(__nv_bfloat162*)&g_as[9][1][(size_t)m * SD + d0] = t2;
            *(__nv_bfloat162*)&g_as[9][2][(size_t)m * SD + d0] = t3;
        }
        grid_sync();

        #pragma unroll
        for (int lvl = 0; lvl < 5; ++lvl) {
            const int nm = c_nm[lvl];
            const int sk = c_sk[lvl];
            const int jobs = nm * sk * NTILE;
            for (int j = bid; j < jobs; j += G) {
                int tile = j % NTILE;
                int r = j / NTILE;
                int kh = r % sk;
                int mat = r / sk;
                do_tile(t, c_sid[lvl][mat], mat, tile, kh, sk, W0, Ws, &sm);
            }
            grid_sync();
        }
    }
}

// ---------------------------------------------------------------------------
// K5: mean over T, decoder, log_softmax, new_hidden.
// ---------------------------------------------------------------------------
__global__ void final_kernel(const float* __restrict__ masks,
                             const float* __restrict__ decW,
                             const float* __restrict__ decb,
                             float* __restrict__ out) {
    int b = blockIdx.x;
    int tid = threadIdx.x;
    __shared__ float sout[DD];
    __shared__ float lg[NCC];
    __shared__ float lse;

    float mask_last = masks[b * TT + TT - 1];
    for (int d = tid; d < DD; d += blockDim.x) {
        float ms = 0.f;
        #pragma unroll
        for (int j = 1; j <= 8; j++) ms += g_state[j][b * SD + d];
        ms *= 0.125f;
        float last_raw = ms * mask_last;
        float acc = last_raw;
        for (int t = 0; t < TT - 1; t++)
            acc += g_hiddens[(size_t)t * BB * DD + b * DD + d] * masks[b * TT + t];
        sout[d] = acc * (1.f / TT);
        out[NCC * BB + b * DD + d] = last_raw;
    }
    __syncthreads();

    for (int c = tid; c < NCC; c += blockDim.x) {
        float acc = decb[c];
        const float* w = decW + (size_t)c * DD;
        for (int d = 0; d < DD; d++) acc = fmaf(sout[d], w[d], acc);
        lg[c] = acc;
    }
    __syncthreads();

    if (tid == 0) {
        float mx = lg[0];
        for (int c = 1; c < NCC; c++) mx = fmaxf(mx, lg[c]);
        float s = 0.f;
        for (int c = 0; c < NCC; c++) s += expf(lg[c] - mx);
        lse = mx + logf(s);
    }
    __syncthreads();

    for (int c = tid; c < NCC; c += blockDim.x)
        out[b * NCC + c] = lg[c] - lse;
}

// ---------------------------------------------------------------------------
// Host launcher
// ---------------------------------------------------------------------------
extern "C" void kernel_launch(void* const* d_in, const int* in_sizes, int n_in,
                              void* d_out, int out_size) {
    const int*   tokens = (const int*)  d_in[0];
    const float* masks  = (const float*)d_in[1];
    const int*   pos    = (const int*)  d_in[2];
    const int*   ner    = (const int*)  d_in[3];
    const float* hidden = (const float*)d_in[4];
    const float* encW   = (const float*)d_in[5];
    const float* nerW   = (const float*)d_in[6];
    const float* posW   = (const float*)d_in[7];
    const float* aggW   = (const float*)d_in[8];
    const float* aggb   = (const float*)d_in[9];
    const float* W0     = (const float*)d_in[10];
    const float* Ws     = (const float*)d_in[11];
    const float* decW   = (const float*)d_in[12];
    const float* decb   = (const float*)d_in[13];
    float* out = (float*)d_out;

    static int s_grid = 0;
    if (s_grid == 0) {
        int dev = 0;
        cudaGetDevice(&dev);
        cudaDeviceProp prop;
        cudaGetDeviceProperties(&prop, dev);
        s_grid = 2 * prop.multiProcessorCount;
    }

    float *p_combined, *p_x, *p_xw0;
    cudaGetSymbolAddress((void**)&p_combined, g_combined);
    cudaGetSymbolAddress((void**)&p_x,        g_x);
    cudaGetSymbolAddress((void**)&p_xw0,      g_xw0);

    // 1) gather embeddings
    gather_kernel<<<TT * BB, 128>>>(tokens, ner, pos, encW, nerW, posW);

    // 2) agg linear: x = combined @ aggW^T + aggb   [8192, 850]
    {
        dim3 g((DD + 63) / 64, (TT * BB) / 64);
        gemm_tile<true, true><<<g, 256>>>(p_combined, aggW, aggb, p_x,
                                          TT * BB, DD, CIN, CIN, CIN, DD);
    }
    // 3) xw0 = x @ W0[0:DD, :]   [8192, 1700]
    {
        dim3 g((D2 + 63) / 64, (TT * BB) / 64);
        gemm_tile<false, false><<<g, 256>>>(p_x, W0, nullptr, p_xw0,
                                            TT * BB, D2, DD, DD, D2, D2);
    }

    // 4) whole recurrence in ONE persistent kernel (fp32 engine, R7 skeleton)
    recur_persist<<<s_grid, 256>>>(W0, Ws, hidden);

    // 5) mean over T, decoder, log_softmax, new_hidden
    final_kernel<<<BB, 256>>>(masks, decW, decb, out);
}